// round 12
// baseline (speedup 1.0000x reference)
#include <cuda_runtime.h>
#include <cuda_bf16.h>
#include <cstdint>

#define D_DIM 128
#define MAX_NODES 50000
#define MAX_EDGES 800000
#define SMS 132        // padded smem row stride (floats)
#define TROWS 64       // A-tile rows per gemm block
#define SCAN_THREADS 1024
#define GEMM_GRID 304  // 2 CTAs/SM * 152 SMs

__device__ float g_agg[MAX_NODES * D_DIM];
__device__ int   g_count[MAX_NODES];
__device__ int   g_offset[MAX_NODES + 1];
__device__ int   g_cursor[MAX_NODES];
__device__ int   g_elist[MAX_EDGES];   // src ids grouped by dst
__device__ int   g_idx64;

// ---------------------------------------------------------------------------
// Detect int64 vs int32 indices (JAX without x64 silently emits i32).
// ---------------------------------------------------------------------------
__global__ void detect_kernel(const void* srcp, int n_edges, int n_nodes) {
    if (threadIdx.x == 0) g_idx64 = 1;
    __syncthreads();
    int n = n_edges < 64 ? n_edges : 64;
    if (threadIdx.x < n) {
        long long v = ((const long long*)srcp)[threadIdx.x];
        if (v < 0 || v >= (long long)n_nodes) g_idx64 = 0;
    }
}

__global__ void zero_count_kernel(int n_nodes) {
    int i = blockIdx.x * blockDim.x + threadIdx.x;
    if (i < n_nodes) g_count[i] = 0;
}

// ---------------------------------------------------------------------------
// Histogram of dst degrees, 4 edges per thread (batched loads -> MLP).
// ---------------------------------------------------------------------------
__global__ void hist_kernel(const void* __restrict__ dstp, int n_edges) {
    int e0 = (blockIdx.x * blockDim.x + threadIdx.x) * 4;
    if (e0 >= n_edges) return;
    int d[4];
    int m = n_edges - e0; if (m > 4) m = 4;
    if (g_idx64) {
        const long long* dp = (const long long*)dstp;
        #pragma unroll
        for (int j = 0; j < 4; j++) d[j] = (int)dp[min(e0 + j, n_edges - 1)];
    } else {
        const int* dp = (const int*)dstp;
        #pragma unroll
        for (int j = 0; j < 4; j++) d[j] = dp[min(e0 + j, n_edges - 1)];
    }
    #pragma unroll
    for (int j = 0; j < 4; j++)
        if (j < m) atomicAdd(&g_count[d[j]], 1);
}

// ---------------------------------------------------------------------------
// Single-block exclusive scan of g_count -> g_offset / g_cursor.
// ---------------------------------------------------------------------------
__global__ void scan_kernel(int n_nodes) {
    __shared__ int s[SCAN_THREADS];
    int t = threadIdx.x;
    int chunk = (n_nodes + SCAN_THREADS - 1) / SCAN_THREADS;
    int beg = t * chunk;
    int end = beg + chunk; if (end > n_nodes) end = n_nodes;

    int sum = 0;
    for (int i = beg; i < end; i++) sum += g_count[i];
    s[t] = sum;
    __syncthreads();
    for (int off = 1; off < SCAN_THREADS; off <<= 1) {
        int v = (t >= off) ? s[t - off] : 0;
        __syncthreads();
        s[t] += v;
        __syncthreads();
    }
    int run = (t == 0) ? 0 : s[t - 1];
    for (int i = beg; i < end; i++) {
        g_offset[i] = run;
        g_cursor[i] = run;
        run += g_count[i];
    }
    if (t == SCAN_THREADS - 1) g_offset[n_nodes] = s[SCAN_THREADS - 1];
}

// ---------------------------------------------------------------------------
// Placement: bucket src ids by dst, 4 edges per thread.
// ---------------------------------------------------------------------------
__global__ void place_kernel(const void* __restrict__ srcp,
                             const void* __restrict__ dstp, int n_edges) {
    int e0 = (blockIdx.x * blockDim.x + threadIdx.x) * 4;
    if (e0 >= n_edges) return;
    int s[4], d[4];
    int m = n_edges - e0; if (m > 4) m = 4;
    if (g_idx64) {
        const long long* sp = (const long long*)srcp;
        const long long* dp = (const long long*)dstp;
        #pragma unroll
        for (int j = 0; j < 4; j++) {
            int e = min(e0 + j, n_edges - 1);
            s[j] = (int)sp[e]; d[j] = (int)dp[e];
        }
    } else {
        const int* sp = (const int*)srcp;
        const int* dp = (const int*)dstp;
        #pragma unroll
        for (int j = 0; j < 4; j++) {
            int e = min(e0 + j, n_edges - 1);
            s[j] = sp[e]; d[j] = dp[e];
        }
    }
    #pragma unroll
    for (int j = 0; j < 4; j++)
        if (j < m) {
            int pos = atomicAdd(&g_cursor[d[j]], 1);
            g_elist[pos] = s[j];
        }
}

// ---------------------------------------------------------------------------
// Gather: one warp per node, register accumulation, atomic-free.
// Edges in batches of 8 (then 4, then scalar): all batch loads are
// independent LDG.128s -> MLP=8, same trick that brought the scatter to the
// LTS cap. Writes every row, so no separate zero pass for g_agg.
// Traffic: 410MB reads + 25.6MB writes (vs 410+410 for the atomic scatter).
// ---------------------------------------------------------------------------
__global__ void gather_kernel(const float* __restrict__ x, int n_nodes) {
    int node = blockIdx.x * (blockDim.x >> 5) + (threadIdx.x >> 5);
    if (node >= n_nodes) return;
    int lane = threadIdx.x & 31;

    int beg = g_offset[node];
    int end = g_offset[node + 1];

    float4 acc = make_float4(0.f, 0.f, 0.f, 0.f);
    int i = beg;

    for (; i + 8 <= end; i += 8) {
        int s[8];
        #pragma unroll
        for (int j = 0; j < 8; j++) s[j] = __ldg(&g_elist[i + j]);
        float4 v[8];
        #pragma unroll
        for (int j = 0; j < 8; j++)
            v[j] = ((const float4*)(x + (long long)s[j] * D_DIM))[lane];
        #pragma unroll
        for (int j = 0; j < 8; j++) {
            acc.x += v[j].x; acc.y += v[j].y;
            acc.z += v[j].z; acc.w += v[j].w;
        }
    }
    if (i + 4 <= end) {
        int s[4];
        #pragma unroll
        for (int j = 0; j < 4; j++) s[j] = __ldg(&g_elist[i + j]);
        float4 v[4];
        #pragma unroll
        for (int j = 0; j < 4; j++)
            v[j] = ((const float4*)(x + (long long)s[j] * D_DIM))[lane];
        #pragma unroll
        for (int j = 0; j < 4; j++) {
            acc.x += v[j].x; acc.y += v[j].y;
            acc.z += v[j].z; acc.w += v[j].w;
        }
        i += 4;
    }
    for (; i < end; i++) {
        int s0 = __ldg(&g_elist[i]);
        float4 v0 = ((const float4*)(x + (long long)s0 * D_DIM))[lane];
        acc.x += v0.x; acc.y += v0.y; acc.z += v0.z; acc.w += v0.w;
    }

    ((float4*)(g_agg + (long long)node * D_DIM))[lane] = acc;
}

// ---------------------------------------------------------------------------
// Persistent tf32 tensor-core GEMM + ReLU + residual:
//   out[n][j] = relu( sum_k agg[n][k] * W[j][k] ) + x[n][j]
// Grid = GEMM_GRID (2 CTAs/SM); each CTA fills the W tile ONCE and
// grid-strides over 64-row A tiles, amortizing the 64KB W fill ~2.6x.
// mma.sync.m16n8k8.row.col; warp tile 32x32; stride-132 padding keeps
// fragment LDS reads conflict-free.
// ---------------------------------------------------------------------------
__global__ __launch_bounds__(256, 2)
void gemm_tf32_kernel(const float* __restrict__ x,
                      const float* __restrict__ W,
                      float* __restrict__ out,
                      int n_nodes, int n_tiles) {
    extern __shared__ float smem[];
    float* As = smem;                // [TROWS][SMS]
    float* Bs = smem + TROWS * SMS;  // [128][SMS]

    int tid = threadIdx.x;

    // Fill Bs (full W) once, rounding to tf32.
    #pragma unroll
    for (int i = tid; i < 128 * (D_DIM / 4); i += 256) {
        int r = i >> 5;
        int k = (i & 31) * 4;
        float4 b = *(const float4*)&W[r * D_DIM + k];
        uint32_t t;
        asm("cvt.rna.tf32.f32 %0, %1;" : "=r"(t) : "f"(b.x)); b.x = __uint_as_float(t);
        asm("cvt.rna.tf32.f32 %0, %1;" : "=r"(t) : "f"(b.y)); b.y = __uint_as_float(t);
        asm("cvt.rna.tf32.f32 %0, %1;" : "=r"(t) : "f"(b.z)); b.z = __uint_as_float(t);
        asm("cvt.rna.tf32.f32 %0, %1;" : "=r"(t) : "f"(b.w)); b.w = __uint_as_float(t);
        *(float4*)&Bs[r * SMS + k] = b;
    }

    int warp = tid >> 5;
    int lane = tid & 31;
    int g   = lane >> 2;
    int tig = lane & 3;
    int wr = (warp >> 2) * 32;
    int wc = (warp & 3) * 32;

    for (int tile = blockIdx.x; tile < n_tiles; tile += gridDim.x) {
        int row0 = tile * TROWS;

        __syncthreads();   // previous iteration's As readers done (also orders Bs fill)
        #pragma unroll
        for (int i = tid; i < TROWS * (D_DIM / 4); i += 256) {
            int r = i >> 5;
            int k = (i & 31) * 4;
            int row = row0 + r;
            float4 a = (row < n_nodes)
                ? *(const float4*)&g_agg[(long long)row * D_DIM + k]
                : make_float4(0.f, 0.f, 0.f, 0.f);
            uint32_t t;
            asm("cvt.rna.tf32.f32 %0, %1;" : "=r"(t) : "f"(a.x)); a.x = __uint_as_float(t);
            asm("cvt.rna.tf32.f32 %0, %1;" : "=r"(t) : "f"(a.y)); a.y = __uint_as_float(t);
            asm("cvt.rna.tf32.f32 %0, %1;" : "=r"(t) : "f"(a.z)); a.z = __uint_as_float(t);
            asm("cvt.rna.tf32.f32 %0, %1;" : "=r"(t) : "f"(a.w)); a.w = __uint_as_float(t);
            *(float4*)&As[r * SMS + k] = a;
        }
        __syncthreads();

        float acc[2][4][4];
        #pragma unroll
        for (int mi = 0; mi < 2; mi++)
            #pragma unroll
            for (int ni = 0; ni < 4; ni++)
                #pragma unroll
                for (int c = 0; c < 4; c++) acc[mi][ni][c] = 0.f;

        #pragma unroll 4
        for (int k0 = 0; k0 < D_DIM; k0 += 8) {
            uint32_t a[2][4], b[4][2];
            #pragma unroll
            for (int mi = 0; mi < 2; mi++) {
                const float* base = &As[(wr + mi * 16 + g) * SMS + k0 + tig];
                a[mi][0] = __float_as_uint(base[0]);
                a[mi][1] = __float_as_uint(base[8 * SMS]);
                a[mi][2] = __float_as_uint(base[4]);
                a[mi][3] = __float_as_uint(base[8 * SMS + 4]);
            }
            #pragma unroll
            for (int ni = 0; ni < 4; ni++) {
                const float* base = &Bs[(wc + ni * 8 + g) * SMS + k0 + tig];
                b[ni][0] = __float_as_uint(base[0]);
                b[ni][1] = __float_as_uint(base[4]);
            }
            #pragma unroll
            for (int mi = 0; mi < 2; mi++)
                #pragma unroll
                for (int ni = 0; ni < 4; ni++) {
                    asm volatile(
                        "mma.sync.aligned.m16n8k8.row.col.f32.tf32.tf32.f32 "
                        "{%0,%1,%2,%3}, {%4,%5,%6,%7}, {%8,%9}, {%0,%1,%2,%3};"
                        : "+f"(acc[mi][ni][0]), "+f"(acc[mi][ni][1]),
                          "+f"(acc[mi][ni][2]), "+f"(acc[mi][ni][3])
                        : "r"(a[mi][0]), "r"(a[mi][1]), "r"(a[mi][2]), "r"(a[mi][3]),
                          "r"(b[ni][0]), "r"(b[ni][1]));
                }
        }

        #pragma unroll
        for (int mi = 0; mi < 2; mi++) {
            #pragma unroll
            for (int half = 0; half < 2; half++) {
                int row = row0 + wr + mi * 16 + g + half * 8;
                if (row < n_nodes) {
                    #pragma unroll
                    for (int ni = 0; ni < 4; ni++) {
                        int col = wc + ni * 8 + tig * 2;
                        long long base = (long long)row * D_DIM + col;
                        float2 xr = *(const float2*)&x[base];
                        float2 o;
                        o.x = fmaxf(acc[mi][ni][half * 2 + 0], 0.f) + xr.x;
                        o.y = fmaxf(acc[mi][ni][half * 2 + 1], 0.f) + xr.y;
                        *(float2*)&out[base] = o;
                    }
                }
            }
        }
    }
}

// ---------------------------------------------------------------------------
extern "C" void kernel_launch(void* const* d_in, const int* in_sizes, int n_in,
                              void* d_out, int out_size) {
    const float* x   = (const float*)d_in[0];
    const void*  src = d_in[1];
    const void*  dst = d_in[2];
    const float* W   = (const float*)d_in[3];
    float* out = (float*)d_out;

    int n_nodes = in_sizes[0] / D_DIM;
    int n_edges = in_sizes[1];

    static const size_t smem_bytes = (TROWS + 128) * SMS * sizeof(float); // ~101KB
    cudaFuncSetAttribute(gemm_tf32_kernel,
                         cudaFuncAttributeMaxDynamicSharedMemorySize,
                         (int)smem_bytes);

    // 1. Index dtype detection + count zeroing (tiny).
    detect_kernel<<<1, 64>>>(src, n_edges, n_nodes);
    zero_count_kernel<<<(n_nodes + 255) / 256, 256>>>(n_nodes);

    // 2. CSR build: histogram -> scan -> placement (4 edges/thread).
    int e4blocks = (n_edges + 4 * 256 - 1) / (4 * 256);
    hist_kernel<<<e4blocks, 256>>>(dst, n_edges);
    scan_kernel<<<1, SCAN_THREADS>>>(n_nodes);
    place_kernel<<<e4blocks, 256>>>(src, dst, n_edges);

    // 3. Atomic-free gather, one warp per node, MLP-8 batches.
    {
        int warps_per_block = 8;
        int blocks = (n_nodes + warps_per_block - 1) / warps_per_block;
        gather_kernel<<<blocks, warps_per_block * 32>>>(x, n_nodes);
    }

    // 4. Persistent tf32 tensor GEMM + ReLU + residual.
    {
        int n_tiles = (n_nodes + TROWS - 1) / TROWS;
        int grid = GEMM_GRID < n_tiles ? GEMM_GRID : n_tiles;
        gemm_tf32_kernel<<<grid, 256, smem_bytes>>>(x, W, out, n_nodes, n_tiles);
    }
}

// round 14
// speedup vs baseline: 1.8897x; 1.8897x over previous
#include <cuda_runtime.h>
#include <cuda_bf16.h>
#include <cstdint>

#define D_DIM 128
#define MAX_NODES 50000
#define MAX_EDGES 800000
#define SMS 132        // padded smem row stride (floats)
#define TROWS 64       // A-tile rows per gemm block
#define GEMM_GRID 304  // 2 CTAs/SM * 152 SMs
#define SCAN_CHUNK 1024
#define MAX_SCAN_BLK 256

__device__ float g_agg[MAX_NODES * D_DIM];
__device__ int   g_count[MAX_NODES];
__device__ int   g_offset[MAX_NODES + 1];
__device__ int   g_cursor[MAX_NODES];
__device__ int   g_elist[MAX_EDGES];   // src ids grouped by dst
__device__ int   g_bsum[MAX_SCAN_BLK];
__device__ int   g_bpre[MAX_SCAN_BLK];
__device__ int   g_idx64;

// ---------------------------------------------------------------------------
// Detect int64 vs int32 indices (JAX without x64 silently emits i32).
// ---------------------------------------------------------------------------
__global__ void detect_kernel(const void* srcp, int n_edges, int n_nodes) {
    if (threadIdx.x == 0) g_idx64 = 1;
    __syncthreads();
    int n = n_edges < 64 ? n_edges : 64;
    if (threadIdx.x < n) {
        long long v = ((const long long*)srcp)[threadIdx.x];
        if (v < 0 || v >= (long long)n_nodes) g_idx64 = 0;
    }
}

__global__ void zero_count_kernel(int n_nodes) {
    int i = blockIdx.x * blockDim.x + threadIdx.x;
    if (i < n_nodes) g_count[i] = 0;
}

// ---------------------------------------------------------------------------
// Histogram of dst degrees, 4 edges per thread (batched loads -> MLP).
// ---------------------------------------------------------------------------
__global__ void hist_kernel(const void* __restrict__ dstp, int n_edges) {
    int e0 = (blockIdx.x * blockDim.x + threadIdx.x) * 4;
    if (e0 >= n_edges) return;
    int d[4];
    int m = n_edges - e0; if (m > 4) m = 4;
    if (g_idx64) {
        const long long* dp = (const long long*)dstp;
        #pragma unroll
        for (int j = 0; j < 4; j++) d[j] = (int)dp[min(e0 + j, n_edges - 1)];
    } else {
        const int* dp = (const int*)dstp;
        #pragma unroll
        for (int j = 0; j < 4; j++) d[j] = dp[min(e0 + j, n_edges - 1)];
    }
    #pragma unroll
    for (int j = 0; j < 4; j++)
        if (j < m) atomicAdd(&g_count[d[j]], 1);
}

// ---------------------------------------------------------------------------
// Device-wide scan, 3 phases. Chunk = 1024 counts per block (256 thr x 4).
// ---------------------------------------------------------------------------
__global__ void scan_part1(int n_nodes) {        // block reduce -> g_bsum
    __shared__ int s[256];
    int t = threadIdx.x;
    int base = blockIdx.x * SCAN_CHUNK + t * 4;
    int sum = 0;
    #pragma unroll
    for (int j = 0; j < 4; j++) {
        int i = base + j;
        if (i < n_nodes) sum += g_count[i];
    }
    s[t] = sum;
    __syncthreads();
    #pragma unroll
    for (int off = 128; off > 0; off >>= 1) {
        if (t < off) s[t] += s[t + off];
        __syncthreads();
    }
    if (t == 0) g_bsum[blockIdx.x] = s[0];
}

__global__ void scan_part2(int n_blocks, int n_nodes) {  // scan block sums
    __shared__ int s[MAX_SCAN_BLK];
    int t = threadIdx.x;
    s[t] = (t < n_blocks) ? g_bsum[t] : 0;
    __syncthreads();
    #pragma unroll
    for (int off = 1; off < MAX_SCAN_BLK; off <<= 1) {
        int v = (t >= off) ? s[t - off] : 0;
        __syncthreads();
        s[t] += v;
        __syncthreads();
    }
    if (t < n_blocks) g_bpre[t] = (t == 0) ? 0 : s[t - 1];
    if (t == MAX_SCAN_BLK - 1) g_offset[n_nodes] = s[MAX_SCAN_BLK - 1];
}

__global__ void scan_part3(int n_nodes) {        // local scan + block prefix
    __shared__ int s[256];
    int t = threadIdx.x;
    int base = blockIdx.x * SCAN_CHUNK + t * 4;

    int c[4], local = 0;
    #pragma unroll
    for (int j = 0; j < 4; j++) {
        int i = base + j;
        c[j] = (i < n_nodes) ? g_count[i] : 0;
        local += c[j];
    }
    s[t] = local;
    __syncthreads();
    #pragma unroll
    for (int off = 1; off < 256; off <<= 1) {
        int v = (t >= off) ? s[t - off] : 0;
        __syncthreads();
        s[t] += v;
        __syncthreads();
    }
    int run = g_bpre[blockIdx.x] + ((t == 0) ? 0 : s[t - 1]);
    #pragma unroll
    for (int j = 0; j < 4; j++) {
        int i = base + j;
        if (i < n_nodes) {
            g_offset[i] = run;
            g_cursor[i] = run;
            run += c[j];
        }
    }
}

// ---------------------------------------------------------------------------
// Placement: bucket src ids by dst, 4 edges per thread.
// ---------------------------------------------------------------------------
__global__ void place_kernel(const void* __restrict__ srcp,
                             const void* __restrict__ dstp, int n_edges) {
    int e0 = (blockIdx.x * blockDim.x + threadIdx.x) * 4;
    if (e0 >= n_edges) return;
    int s[4], d[4];
    int m = n_edges - e0; if (m > 4) m = 4;
    if (g_idx64) {
        const long long* sp = (const long long*)srcp;
        const long long* dp = (const long long*)dstp;
        #pragma unroll
        for (int j = 0; j < 4; j++) {
            int e = min(e0 + j, n_edges - 1);
            s[j] = (int)sp[e]; d[j] = (int)dp[e];
        }
    } else {
        const int* sp = (const int*)srcp;
        const int* dp = (const int*)dstp;
        #pragma unroll
        for (int j = 0; j < 4; j++) {
            int e = min(e0 + j, n_edges - 1);
            s[j] = sp[e]; d[j] = dp[e];
        }
    }
    #pragma unroll
    for (int j = 0; j < 4; j++)
        if (j < m) {
            int pos = atomicAdd(&g_cursor[d[j]], 1);
            g_elist[pos] = s[j];
        }
}

// ---------------------------------------------------------------------------
// Gather: one warp per node, register accumulation, atomic-free.
// Edge batches of 8 independent LDG.128s (MLP=8). Writes every row, so no
// zero pass. Traffic: 410MB reads + 25.6MB writes.
// ---------------------------------------------------------------------------
__global__ void gather_kernel(const float* __restrict__ x, int n_nodes) {
    int node = blockIdx.x * (blockDim.x >> 5) + (threadIdx.x >> 5);
    if (node >= n_nodes) return;
    int lane = threadIdx.x & 31;

    int beg = g_offset[node];
    int end = g_offset[node + 1];

    float4 acc = make_float4(0.f, 0.f, 0.f, 0.f);
    int i = beg;

    for (; i + 8 <= end; i += 8) {
        int s[8];
        #pragma unroll
        for (int j = 0; j < 8; j++) s[j] = __ldg(&g_elist[i + j]);
        float4 v[8];
        #pragma unroll
        for (int j = 0; j < 8; j++)
            v[j] = ((const float4*)(x + (long long)s[j] * D_DIM))[lane];
        #pragma unroll
        for (int j = 0; j < 8; j++) {
            acc.x += v[j].x; acc.y += v[j].y;
            acc.z += v[j].z; acc.w += v[j].w;
        }
    }
    if (i + 4 <= end) {
        int s[4];
        #pragma unroll
        for (int j = 0; j < 4; j++) s[j] = __ldg(&g_elist[i + j]);
        float4 v[4];
        #pragma unroll
        for (int j = 0; j < 4; j++)
            v[j] = ((const float4*)(x + (long long)s[j] * D_DIM))[lane];
        #pragma unroll
        for (int j = 0; j < 4; j++) {
            acc.x += v[j].x; acc.y += v[j].y;
            acc.z += v[j].z; acc.w += v[j].w;
        }
        i += 4;
    }
    for (; i < end; i++) {
        int s0 = __ldg(&g_elist[i]);
        float4 v0 = ((const float4*)(x + (long long)s0 * D_DIM))[lane];
        acc.x += v0.x; acc.y += v0.y; acc.z += v0.z; acc.w += v0.w;
    }

    ((float4*)(g_agg + (long long)node * D_DIM))[lane] = acc;
}

// ---------------------------------------------------------------------------
// Persistent tf32 tensor-core GEMM + ReLU + residual. Each CTA fills the W
// tile once and grid-strides over 64-row A tiles. 2 CTAs/SM.
// ---------------------------------------------------------------------------
__global__ __launch_bounds__(256, 2)
void gemm_tf32_kernel(const float* __restrict__ x,
                      const float* __restrict__ W,
                      float* __restrict__ out,
                      int n_nodes, int n_tiles) {
    extern __shared__ float smem[];
    float* As = smem;                // [TROWS][SMS]
    float* Bs = smem + TROWS * SMS;  // [128][SMS]

    int tid = threadIdx.x;

    #pragma unroll
    for (int i = tid; i < 128 * (D_DIM / 4); i += 256) {
        int r = i >> 5;
        int k = (i & 31) * 4;
        float4 b = *(const float4*)&W[r * D_DIM + k];
        uint32_t t;
        asm("cvt.rna.tf32.f32 %0, %1;" : "=r"(t) : "f"(b.x)); b.x = __uint_as_float(t);
        asm("cvt.rna.tf32.f32 %0, %1;" : "=r"(t) : "f"(b.y)); b.y = __uint_as_float(t);
        asm("cvt.rna.tf32.f32 %0, %1;" : "=r"(t) : "f"(b.z)); b.z = __uint_as_float(t);
        asm("cvt.rna.tf32.f32 %0, %1;" : "=r"(t) : "f"(b.w)); b.w = __uint_as_float(t);
        *(float4*)&Bs[r * SMS + k] = b;
    }

    int warp = tid >> 5;
    int lane = tid & 31;
    int g   = lane >> 2;
    int tig = lane & 3;
    int wr = (warp >> 2) * 32;
    int wc = (warp & 3) * 32;

    for (int tile = blockIdx.x; tile < n_tiles; tile += gridDim.x) {
        int row0 = tile * TROWS;

        __syncthreads();
        #pragma unroll
        for (int i = tid; i < TROWS * (D_DIM / 4); i += 256) {
            int r = i >> 5;
            int k = (i & 31) * 4;
            int row = row0 + r;
            float4 a = (row < n_nodes)
                ? *(const float4*)&g_agg[(long long)row * D_DIM + k]
                : make_float4(0.f, 0.f, 0.f, 0.f);
            uint32_t t;
            asm("cvt.rna.tf32.f32 %0, %1;" : "=r"(t) : "f"(a.x)); a.x = __uint_as_float(t);
            asm("cvt.rna.tf32.f32 %0, %1;" : "=r"(t) : "f"(a.y)); a.y = __uint_as_float(t);
            asm("cvt.rna.tf32.f32 %0, %1;" : "=r"(t) : "f"(a.z)); a.z = __uint_as_float(t);
            asm("cvt.rna.tf32.f32 %0, %1;" : "=r"(t) : "f"(a.w)); a.w = __uint_as_float(t);
            *(float4*)&As[r * SMS + k] = a;
        }
        __syncthreads();

        float acc[2][4][4];
        #pragma unroll
        for (int mi = 0; mi < 2; mi++)
            #pragma unroll
            for (int ni = 0; ni < 4; ni++)
                #pragma unroll
                for (int c = 0; c < 4; c++) acc[mi][ni][c] = 0.f;

        #pragma unroll 4
        for (int k0 = 0; k0 < D_DIM; k0 += 8) {
            uint32_t a[2][4], b[4][2];
            #pragma unroll
            for (int mi = 0; mi < 2; mi++) {
                const float* base = &As[(wr + mi * 16 + g) * SMS + k0 + tig];
                a[mi][0] = __float_as_uint(base[0]);
                a[mi][1] = __float_as_uint(base[8 * SMS]);
                a[mi][2] = __float_as_uint(base[4]);
                a[mi][3] = __float_as_uint(base[8 * SMS + 4]);
            }
            #pragma unroll
            for (int ni = 0; ni < 4; ni++) {
                const float* base = &Bs[(wc + ni * 8 + g) * SMS + k0 + tig];
                b[ni][0] = __float_as_uint(base[0]);
                b[ni][1] = __float_as_uint(base[4]);
            }
            #pragma unroll
            for (int mi = 0; mi < 2; mi++)
                #pragma unroll
                for (int ni = 0; ni < 4; ni++) {
                    asm volatile(
                        "mma.sync.aligned.m16n8k8.row.col.f32.tf32.tf32.f32 "
                        "{%0,%1,%2,%3}, {%4,%5,%6,%7}, {%8,%9}, {%0,%1,%2,%3};"
                        : "+f"(acc[mi][ni][0]), "+f"(acc[mi][ni][1]),
                          "+f"(acc[mi][ni][2]), "+f"(acc[mi][ni][3])
                        : "r"(a[mi][0]), "r"(a[mi][1]), "r"(a[mi][2]), "r"(a[mi][3]),
                          "r"(b[ni][0]), "r"(b[ni][1]));
                }
        }

        #pragma unroll
        for (int mi = 0; mi < 2; mi++) {
            #pragma unroll
            for (int half = 0; half < 2; half++) {
                int row = row0 + wr + mi * 16 + g + half * 8;
                if (row < n_nodes) {
                    #pragma unroll
                    for (int ni = 0; ni < 4; ni++) {
                        int col = wc + ni * 8 + tig * 2;
                        long long base = (long long)row * D_DIM + col;
                        float2 xr = *(const float2*)&x[base];
                        float2 o;
                        o.x = fmaxf(acc[mi][ni][half * 2 + 0], 0.f) + xr.x;
                        o.y = fmaxf(acc[mi][ni][half * 2 + 1], 0.f) + xr.y;
                        *(float2*)&out[base] = o;
                    }
                }
            }
        }
    }
}

// ---------------------------------------------------------------------------
extern "C" void kernel_launch(void* const* d_in, const int* in_sizes, int n_in,
                              void* d_out, int out_size) {
    const float* x   = (const float*)d_in[0];
    const void*  src = d_in[1];
    const void*  dst = d_in[2];
    const float* W   = (const float*)d_in[3];
    float* out = (float*)d_out;

    int n_nodes = in_sizes[0] / D_DIM;
    int n_edges = in_sizes[1];

    static const size_t smem_bytes = (TROWS + 128) * SMS * sizeof(float); // ~101KB
    cudaFuncSetAttribute(gemm_tf32_kernel,
                         cudaFuncAttributeMaxDynamicSharedMemorySize,
                         (int)smem_bytes);

    // 1. Index dtype detection + count zeroing (tiny).
    detect_kernel<<<1, 64>>>(src, n_edges, n_nodes);
    zero_count_kernel<<<(n_nodes + 255) / 256, 256>>>(n_nodes);

    // 2. CSR build: histogram -> device-wide scan -> placement.
    int e4blocks = (n_edges + 4 * 256 - 1) / (4 * 256);
    hist_kernel<<<e4blocks, 256>>>(dst, n_edges);
    int sblocks = (n_nodes + SCAN_CHUNK - 1) / SCAN_CHUNK;   // 49
    scan_part1<<<sblocks, 256>>>(n_nodes);
    scan_part2<<<1, MAX_SCAN_BLK>>>(sblocks, n_nodes);
    scan_part3<<<sblocks, 256>>>(n_nodes);
    place_kernel<<<e4blocks, 256>>>(src, dst, n_edges);

    // 3. Atomic-free gather, one warp per node, MLP-8 batches.
    {
        int warps_per_block = 8;
        int blocks = (n_nodes + warps_per_block - 1) / warps_per_block;
        gather_kernel<<<blocks, warps_per_block * 32>>>(x, n_nodes);
    }

    // 4. Persistent tf32 tensor GEMM + ReLU + residual.
    {
        int n_tiles = (n_nodes + TROWS - 1) / TROWS;
        int grid = GEMM_GRID < n_tiles ? GEMM_GRID : n_tiles;
        gemm_tf32_kernel<<<grid, 256, smem_bytes>>>(x, W, out, n_nodes, n_tiles);
    }
}